// round 15
// baseline (speedup 1.0000x reference)
#include <cuda_runtime.h>
#include <cstdint>

#define N_TOT 16384
#define NPER  2048
#define BATCH 8
#define CH    256
#define KG    16
#define KTOP  512
#define KNNK  32
#define OC    512   // T (256) | P (256)

// ---------------- scratch (no allocs allowed) ----------------
__device__ float g_TP[N_TOT * OC];        // 32 MB
__device__ float g_x1[N_TOT * CH];        // 16 MB
__device__ int   g_perm[BATCH * KTOP];
__device__ float g_xyz_sel[BATCH * KTOP * 3];
__device__ float g_w1t[256 * 64];         // w1 transposed: [k][c]
__device__ float g_w2t[64 * 32];          // w2 transposed: [k][c]

// ---------------- transpose w1/w2 for coalesced MLP reads ----------------
__global__ void transpose_w(const float* __restrict__ w1,
                            const float* __restrict__ w2) {
    int t = blockIdx.x * 256 + threadIdx.x;
    if (t < 64 * 256) {            // w1[r][k], r<64, k<256
        int r = t >> 8, k = t & 255;
        g_w1t[k * 64 + r] = w1[t];
    }
    if (t < 32 * 64) {             // w2[r][k], r<32, k<64
        int r = t >> 6, k = t & 63;
        g_w2t[k * 32 + r] = w2[t];
    }
}

// ---------------- f32x2 helpers (Blackwell FFMA2) ----------------
__device__ __forceinline__ unsigned long long pk2(float lo, float hi) {
    unsigned long long r;
    asm("mov.b64 %0, {%1, %2};" : "=l"(r) : "f"(lo), "f"(hi));
    return r;
}
__device__ __forceinline__ unsigned long long ffma2(unsigned long long a,
                                                    unsigned long long b,
                                                    unsigned long long c) {
    unsigned long long d;
    asm("fma.rn.f32x2 %0, %1, %2, %3;" : "=l"(d) : "l"(a), "l"(b), "l"(c));
    return d;
}
__device__ __forceinline__ void upk2(unsigned long long v, float& lo, float& hi) {
    asm("mov.b64 {%0, %1}, %2;" : "=f"(lo), "=f"(hi) : "l"(v));
}

// ---------------- GEMM: TP[n][o] = sum_k X[n][k] * W[o][k] ----------------
// 128x128 tile (R14's math, proven bitwise-correct) with register hygiene:
// __launch_bounds__(256,2) prevents spills/over-allocation, and unroll-4 on
// the kk loop keeps ap/bd temp live ranges short. Accumulation order identical
// -> bitwise-identical g_TP.
__global__ void __launch_bounds__(256, 2) gemm_tp(
        const float* __restrict__ X,
        const float* __restrict__ theta_w,
        const float* __restrict__ phi_w) {
    __shared__ float As[16][132];   // [k][m], row stride 528B
    __shared__ float Bs[16][132];   // [k][n]
    const int m0 = blockIdx.y * 128;
    const int o0 = blockIdx.x * 128;
    const float* W = (o0 < 256) ? (theta_w + (size_t)o0 * 256)
                                : (phi_w + (size_t)(o0 - 256) * 256);
    const int t  = threadIdx.x;       // 0..255
    const int tx = t & 15;            // col group  (tx*8)
    const int ty = t >> 4;            // row group  (ty*8)

    unsigned long long acc[4][8];     // [row-pair][col]
#pragma unroll
    for (int i = 0; i < 4; i++)
#pragma unroll
        for (int j = 0; j < 8; j++) acc[i][j] = 0ull;

    for (int k0 = 0; k0 < 256; k0 += 16) {
        // A tile: 128 rows x 16 k = 512 float4 loads, 2 per thread
#pragma unroll
        for (int q = 0; q < 2; q++) {
            int s = t + q * 256;
            int row = s >> 2;
            int kc = (s & 3) * 4;
            float4 v = *reinterpret_cast<const float4*>(
                X + (size_t)(m0 + row) * 256 + k0 + kc);
            As[kc + 0][row] = v.x; As[kc + 1][row] = v.y;
            As[kc + 2][row] = v.z; As[kc + 3][row] = v.w;
        }
        // B tile: 128 rows x 16 k = 512 float4 loads, 2 per thread
#pragma unroll
        for (int q = 0; q < 2; q++) {
            int s = t + q * 256;
            int row = s >> 2;
            int kc = (s & 3) * 4;
            float4 v = *reinterpret_cast<const float4*>(
                W + (size_t)row * 256 + k0 + kc);
            Bs[kc + 0][row] = v.x; Bs[kc + 1][row] = v.y;
            Bs[kc + 2][row] = v.z; Bs[kc + 3][row] = v.w;
        }
        __syncthreads();
#pragma unroll 4
        for (int kk = 0; kk < 16; kk++) {
            ulonglong2 a01 = *reinterpret_cast<const ulonglong2*>(&As[kk][ty * 8]);
            ulonglong2 a23 = *reinterpret_cast<const ulonglong2*>(&As[kk][ty * 8 + 4]);
            float4 b0 = *reinterpret_cast<const float4*>(&Bs[kk][tx * 8]);
            float4 b1 = *reinterpret_cast<const float4*>(&Bs[kk][tx * 8 + 4]);
            unsigned long long ap[4] = {a01.x, a01.y, a23.x, a23.y};
            unsigned long long bd[8] = {pk2(b0.x, b0.x), pk2(b0.y, b0.y),
                                        pk2(b0.z, b0.z), pk2(b0.w, b0.w),
                                        pk2(b1.x, b1.x), pk2(b1.y, b1.y),
                                        pk2(b1.z, b1.z), pk2(b1.w, b1.w)};
#pragma unroll
            for (int i = 0; i < 4; i++)
#pragma unroll
                for (int j = 0; j < 8; j++)
                    acc[i][j] = ffma2(ap[i], bd[j], acc[i][j]);
        }
        __syncthreads();
    }
#pragma unroll
    for (int i = 0; i < 4; i++) {
        int r0 = m0 + ty * 8 + 2 * i;
#pragma unroll
        for (int h = 0; h < 2; h++) {
            float lo[8], hi[8];
#pragma unroll
            for (int j = 0; j < 8; j++) upk2(acc[i][j], lo[j], hi[j]);
            const float* v = h ? hi : lo;
            *reinterpret_cast<float4*>(&g_TP[(size_t)(r0 + h) * OC + o0 + tx * 8]) =
                make_float4(v[0], v[1], v[2], v[3]);
            *reinterpret_cast<float4*>(&g_TP[(size_t)(r0 + h) * OC + o0 + tx * 8 + 4]) =
                make_float4(v[4], v[5], v[6], v[7]);
        }
    }
}

// ---------------- EdgeConv max + residual + score MLP (fused) ----------------
// 4 nodes per block (R13-passing). Per-(n,c) arithmetic unchanged.
__global__ void edgemax_mlp(const float* __restrict__ x,
                            const int* __restrict__ edge_src,
                            const float* __restrict__ theta_b,
                            const float* __restrict__ phi_b,
                            const float* __restrict__ b1,
                            const float* __restrict__ g1, const float* __restrict__ be1,
                            const float* __restrict__ m1, const float* __restrict__ v1,
                            const float* __restrict__ b2,
                            const float* __restrict__ g2, const float* __restrict__ be2,
                            const float* __restrict__ m2, const float* __restrict__ v2,
                            const float* __restrict__ w3, const float* __restrict__ b3,
                            float* __restrict__ score_out) {
    const int n0 = blockIdx.x * 4;
    const int tid = threadIdx.x;   // 0..255
    __shared__ int   srcs[4][KG];
    __shared__ float sx[4][CH];
    __shared__ float st1[4][64];
    __shared__ float st2[4][32];
    if (tid < 4 * KG) srcs[tid >> 4][tid & 15] = edge_src[n0 * KG + tid];
    __syncthreads();
#pragma unroll
    for (int it = 0; it < 4; it++) {
        const int n = n0 + it;
        const int c = tid;
        float mx = -3.4e38f;
#pragma unroll
        for (int j = 0; j < KG; j++)
            mx = fmaxf(mx, g_TP[(size_t)srcs[it][j] * OC + c]);
        float Tn = g_TP[(size_t)n * OC + c];
        float Pn = g_TP[(size_t)n * OC + 256 + c];
        float v = mx - Tn + Pn + theta_b[c] + phi_b[c] + x[(size_t)n * CH + c];
        g_x1[(size_t)n * CH + c] = v;
        sx[it][c] = v;
    }
    __syncthreads();
    {   // stage 1: 4 nodes x 64 outputs = 256 threads, all active
        const int ni = tid >> 6, c = tid & 63;
        float acc = b1[c];
        const float* sxr = sx[ni];
#pragma unroll 8
        for (int k = 0; k < 256; k++) acc = fmaf(g_w1t[k * 64 + c], sxr[k], acc);
        acc = fmaxf(acc, 0.f);
        float rs = 1.f / sqrtf(v1[c] + 1e-5f);
        st1[ni][c] = (acc - m1[c]) * rs * g1[c] + be1[c];
    }
    __syncthreads();
    if (tid < 128) {   // stage 2: 4 nodes x 32 outputs
        const int ni = tid >> 5, c = tid & 31;
        float acc = b2[c];
        const float* s1r = st1[ni];
#pragma unroll
        for (int k = 0; k < 64; k++) acc = fmaf(g_w2t[k * 32 + c], s1r[k], acc);
        acc = fmaxf(acc, 0.f);
        float rs = 1.f / sqrtf(v2[c] + 1e-5f);
        st2[ni][c] = (acc - m2[c]) * rs * g2[c] + be2[c];
    }
    __syncthreads();
    if (tid < 4) {     // stage 3
        float acc = b3[0];
#pragma unroll
        for (int k = 0; k < 32; k++) acc = fmaf(w3[k], st2[tid][k], acc);
        score_out[n0 + tid] = acc;
    }
}

// ---------------- bitonic helpers ----------------
__device__ __forceinline__ void cswap(unsigned long long& a, unsigned long long& b,
                                      unsigned int dir) {
    if ((unsigned int)(a > b) == dir) { unsigned long long t = a; a = b; b = t; }
}

// ---------------- per-batch top-512 (exact jax top_k semantics) ----------------
__global__ void topk_kernel(const float* __restrict__ score,
                            float* __restrict__ topk_vals) {
    __shared__ unsigned long long keys[NPER];
    const int b = blockIdx.x;
    const int tid = threadIdx.x;   // 1024
    for (int i = tid; i < NPER; i += 1024) {
        unsigned int u = __float_as_uint(score[b * NPER + i]);
        u = (u & 0x80000000u) ? ~u : (u | 0x80000000u);   // order-preserving
        keys[i] = ((unsigned long long)(~u) << 32) | (unsigned int)i;  // desc score, asc idx
    }
    for (int size = 2; size < NPER; size <<= 1) {
        unsigned int ddd = 1u ^ (unsigned int)(((unsigned)tid & (unsigned)(size >> 1)) != 0);
        for (int stride = size >> 1; stride > 0; stride >>= 1) {
            __syncthreads();
            int pos = 2 * tid - (tid & (stride - 1));
            cswap(keys[pos], keys[pos + stride], ddd);
        }
    }
    for (int stride = NPER >> 1; stride > 0; stride >>= 1) {
        __syncthreads();
        int pos = 2 * tid - (tid & (stride - 1));
        cswap(keys[pos], keys[pos + stride], 1u);
    }
    __syncthreads();
    if (tid < KTOP) {
        unsigned int idx = (unsigned int)(keys[tid] & 0xffffffffu);
        topk_vals[b * KTOP + tid] = score[b * NPER + idx];
        g_perm[b * KTOP + tid] = b * NPER + (int)idx;
    }
}

// ---------------- gather x_new / x_copy / xyz_sel ----------------
__global__ void gather_kernel(const float* __restrict__ x_origin,
                              const float* __restrict__ xyz,
                              float* __restrict__ out_xnew,
                              float* __restrict__ out_xcopy) {
    const int r = blockIdx.x;        // 0..4095
    const int c = threadIdx.x;       // 256
    const int p = g_perm[r];
    out_xnew[(size_t)r * CH + c]  = g_x1[(size_t)p * CH + c];
    out_xcopy[(size_t)r * CH + c] = x_origin[(size_t)p * CH + c];
    if (c < 3) g_xyz_sel[r * 3 + c] = xyz[p * 3 + c];
}

// ---------------- 32-NN among the 512 selected points (per batch) ----------------
// d2 uses UNFUSED IEEE ops to match XLA's non-contracted sequential reduce so the
// sort keys (and thus the argsort output) are bitwise identical.
__global__ void knn_kernel(float* __restrict__ out_knn) {
    __shared__ float sxp[KTOP], syp[KTOP], szp[KTOP];
    __shared__ unsigned long long keys[KTOP];
    const int b = blockIdx.x >> 9;
    const int i = blockIdx.x & 511;
    const int tid = threadIdx.x;   // 256
    for (int t = tid; t < KTOP; t += 256) {
        int base = (b * KTOP + t) * 3;
        sxp[t] = g_xyz_sel[base]; syp[t] = g_xyz_sel[base + 1]; szp[t] = g_xyz_sel[base + 2];
    }
    __syncthreads();
    float xi = sxp[i], yi = syp[i], zi = szp[i];
    for (int t = tid; t < KTOP; t += 256) {
        float dx = __fsub_rn(xi, sxp[t]);
        float dy = __fsub_rn(yi, syp[t]);
        float dz = __fsub_rn(zi, szp[t]);
        float d2 = __fadd_rn(__fadd_rn(__fmul_rn(dx, dx), __fmul_rn(dy, dy)),
                             __fmul_rn(dz, dz));   // >= 0, unfused IEEE
        keys[t] = ((unsigned long long)__float_as_uint(d2) << 32) | (unsigned int)t;
    }
    for (int size = 2; size < KTOP; size <<= 1) {
        unsigned int ddd = 1u ^ (unsigned int)(((unsigned)tid & (unsigned)(size >> 1)) != 0);
        for (int stride = size >> 1; stride > 0; stride >>= 1) {
            __syncthreads();
            int pos = 2 * tid - (tid & (stride - 1));
            cswap(keys[pos], keys[pos + stride], ddd);
        }
    }
    for (int stride = KTOP >> 1; stride > 0; stride >>= 1) {
        __syncthreads();
        int pos = 2 * tid - (tid & (stride - 1));
        cswap(keys[pos], keys[pos + stride], 1u);
    }
    __syncthreads();
    if (tid < KNNK)
        out_knn[(size_t)blockIdx.x * KNNK + tid] =
            (float)(unsigned int)(keys[tid] & 0xffffffffu);
}

// ---------------- launch ----------------
extern "C" void kernel_launch(void* const* d_in, const int* in_sizes, int n_in,
                              void* d_out, int out_size) {
    const float* x        = (const float*)d_in[0];
    const float* x_origin = (const float*)d_in[1];
    const float* xyz      = (const float*)d_in[2];
    const int*   edge_src = (const int*)d_in[3];
    // d_in[4] = edge_dst (structure known: node n owns edges [16n,16n+16))
    const float* theta_w  = (const float*)d_in[5];
    const float* theta_b  = (const float*)d_in[6];
    const float* phi_w    = (const float*)d_in[7];
    const float* phi_b    = (const float*)d_in[8];
    const float* w1  = (const float*)d_in[9];
    const float* b1  = (const float*)d_in[10];
    const float* g1  = (const float*)d_in[11];
    const float* be1 = (const float*)d_in[12];
    const float* m1  = (const float*)d_in[13];
    const float* v1  = (const float*)d_in[14];
    const float* w2  = (const float*)d_in[15];
    const float* b2  = (const float*)d_in[16];
    const float* g2  = (const float*)d_in[17];
    const float* be2 = (const float*)d_in[18];
    const float* m2  = (const float*)d_in[19];
    const float* v2  = (const float*)d_in[20];
    const float* w3  = (const float*)d_in[21];
    const float* b3  = (const float*)d_in[22];

    float* out = (float*)d_out;
    float* out_knn   = out;                                   // 8*512*32   = 131072
    float* out_xnew  = out + 131072;                          // 8*512*256  = 1048576
    float* out_xcopy = out + 131072 + 1048576;                // 8*512*256  = 1048576
    float* out_score = out + 131072 + 2 * 1048576;            // 8*2048     = 16384
    float* out_topkv = out_score + 16384;                     // 8*512      = 4096

    transpose_w<<<64, 256>>>(w1, w2);
    dim3 ggrid(4, 128);
    gemm_tp<<<ggrid, 256>>>(x, theta_w, phi_w);
    edgemax_mlp<<<N_TOT / 4, 256>>>(x, edge_src, theta_b, phi_b,
                                    b1, g1, be1, m1, v1,
                                    b2, g2, be2, m2, v2, w3, b3, out_score);
    topk_kernel<<<BATCH, 1024>>>(out_score, out_topkv);
    gather_kernel<<<BATCH * KTOP, 256>>>(x_origin, xyz, out_xnew, out_xcopy);
    knn_kernel<<<BATCH * KTOP, 256>>>(out_knn);
}

// round 16
// speedup vs baseline: 1.0875x; 1.0875x over previous
#include <cuda_runtime.h>
#include <cstdint>

#define N_TOT 16384
#define NPER  2048
#define BATCH 8
#define CH    256
#define KG    16
#define KTOP  512
#define KNNK  32
#define OC    512   // T (256) | P (256)

// ---------------- scratch (no allocs allowed) ----------------
__device__ float g_TP[N_TOT * OC];        // 32 MB
__device__ float g_x1[N_TOT * CH];        // 16 MB
__device__ int   g_perm[BATCH * KTOP];
__device__ float g_xyz_sel[BATCH * KTOP * 3];
__device__ float g_w1t[256 * 64];         // w1 transposed: [k][c]
__device__ float g_w2t[64 * 32];          // w2 transposed: [k][c]

// ---------------- transpose w1/w2 for coalesced MLP reads ----------------
__global__ void transpose_w(const float* __restrict__ w1,
                            const float* __restrict__ w2) {
    int t = blockIdx.x * 256 + threadIdx.x;
    if (t < 64 * 256) {            // w1[r][k], r<64, k<256
        int r = t >> 8, k = t & 255;
        g_w1t[k * 64 + r] = w1[t];
    }
    if (t < 32 * 64) {             // w2[r][k], r<32, k<64
        int r = t >> 6, k = t & 63;
        g_w2t[k * 32 + r] = w2[t];
    }
}

// ---------------- f32x2 helpers (Blackwell FFMA2) ----------------
__device__ __forceinline__ unsigned long long pk2(float lo, float hi) {
    unsigned long long r;
    asm("mov.b64 %0, {%1, %2};" : "=l"(r) : "f"(lo), "f"(hi));
    return r;
}
__device__ __forceinline__ unsigned long long ffma2(unsigned long long a,
                                                    unsigned long long b,
                                                    unsigned long long c) {
    unsigned long long d;
    asm("fma.rn.f32x2 %0, %1, %2, %3;" : "=l"(d) : "l"(a), "l"(b), "l"(c));
    return d;
}
__device__ __forceinline__ void upk2(unsigned long long v, float& lo, float& hi) {
    asm("mov.b64 {%0, %1}, %2;" : "=f"(lo), "=f"(hi) : "l"(v));
}

// ---------------- GEMM: TP[n][o] = sum_k X[n][k] * W[o][k] ----------------
// FROZEN at the R9/R13-passing 128x64 form. 128x128 variants regressed twice
// (R14/R15); double-buffer regressed (R10); B-duplication regressed (R12).
__global__ void gemm_tp(const float* __restrict__ X,
                        const float* __restrict__ theta_w,
                        const float* __restrict__ phi_w) {
    __shared__ float As[16][132];   // [k][m], row stride 528B (16B-aligned)
    __shared__ float Bs[16][68];    // [k][n]
    const int m0 = blockIdx.y * 128;
    const int o0 = blockIdx.x * 64;
    const float* W = (o0 < 256) ? (theta_w + (size_t)o0 * 256)
                                : (phi_w + (size_t)(o0 - 256) * 256);
    const int t  = threadIdx.x;       // 0..255
    const int tx = t & 15;            // col group  (tx*4)
    const int ty = t >> 4;            // row group  (ty*8)

    unsigned long long acc[4][4];     // [row-pair][col]
#pragma unroll
    for (int i = 0; i < 4; i++)
#pragma unroll
        for (int j = 0; j < 4; j++) acc[i][j] = 0ull;

    for (int k0 = 0; k0 < 256; k0 += 16) {
        // A tile: 128 rows x 16 k = 512 float4 loads, 2 per thread
#pragma unroll
        for (int q = 0; q < 2; q++) {
            int s = t + q * 256;
            int row = s >> 2;
            int kc = (s & 3) * 4;
            float4 v = *reinterpret_cast<const float4*>(
                X + (size_t)(m0 + row) * 256 + k0 + kc);
            As[kc + 0][row] = v.x; As[kc + 1][row] = v.y;
            As[kc + 2][row] = v.z; As[kc + 3][row] = v.w;
        }
        // B tile: 64 rows x 16 k = 256 float4 loads, 1 per thread
        {
            int row = t >> 2;
            int kc = (t & 3) * 4;
            float4 v = *reinterpret_cast<const float4*>(
                W + (size_t)row * 256 + k0 + kc);
            Bs[kc + 0][row] = v.x; Bs[kc + 1][row] = v.y;
            Bs[kc + 2][row] = v.z; Bs[kc + 3][row] = v.w;
        }
        __syncthreads();
#pragma unroll
        for (int kk = 0; kk < 16; kk++) {
            ulonglong2 a01 = *reinterpret_cast<const ulonglong2*>(&As[kk][ty * 8]);
            ulonglong2 a23 = *reinterpret_cast<const ulonglong2*>(&As[kk][ty * 8 + 4]);
            float4 b = *reinterpret_cast<const float4*>(&Bs[kk][tx * 4]);
            unsigned long long ap[4] = {a01.x, a01.y, a23.x, a23.y};
            unsigned long long bd[4] = {pk2(b.x, b.x), pk2(b.y, b.y),
                                        pk2(b.z, b.z), pk2(b.w, b.w)};
#pragma unroll
            for (int i = 0; i < 4; i++)
#pragma unroll
                for (int j = 0; j < 4; j++)
                    acc[i][j] = ffma2(ap[i], bd[j], acc[i][j]);
        }
        __syncthreads();
    }
#pragma unroll
    for (int i = 0; i < 4; i++) {
        int r0 = m0 + ty * 8 + 2 * i;
        float lo[4], hi[4];
#pragma unroll
        for (int j = 0; j < 4; j++) upk2(acc[i][j], lo[j], hi[j]);
        *reinterpret_cast<float4*>(&g_TP[(size_t)r0 * OC + o0 + tx * 4]) =
            make_float4(lo[0], lo[1], lo[2], lo[3]);
        *reinterpret_cast<float4*>(&g_TP[(size_t)(r0 + 1) * OC + o0 + tx * 4]) =
            make_float4(hi[0], hi[1], hi[2], hi[3]);
    }
}

// ---------------- EdgeConv max + residual + score MLP (fused) ----------------
// 8 nodes per block: per-node w1t traffic halves vs the R13 4-node version,
// and in stage 1 each thread computes TWO outputs (nodes ni and ni+4) sharing
// the same w1t[k*64+c] load. Each output keeps its own accumulator over the
// identical ascending-k fmaf chain -> scores bitwise-identical.
__global__ void edgemax_mlp(const float* __restrict__ x,
                            const int* __restrict__ edge_src,
                            const float* __restrict__ theta_b,
                            const float* __restrict__ phi_b,
                            const float* __restrict__ b1,
                            const float* __restrict__ g1, const float* __restrict__ be1,
                            const float* __restrict__ m1, const float* __restrict__ v1,
                            const float* __restrict__ b2,
                            const float* __restrict__ g2, const float* __restrict__ be2,
                            const float* __restrict__ m2, const float* __restrict__ v2,
                            const float* __restrict__ w3, const float* __restrict__ b3,
                            float* __restrict__ score_out) {
    const int n0 = blockIdx.x * 8;
    const int tid = threadIdx.x;   // 0..255
    __shared__ int   srcs[8][KG];
    __shared__ float sx[8][CH];
    __shared__ float st1[8][64];
    __shared__ float st2[8][32];
    if (tid < 8 * KG) srcs[tid >> 4][tid & 15] = edge_src[n0 * KG + tid];
    __syncthreads();
#pragma unroll
    for (int it = 0; it < 8; it++) {
        const int n = n0 + it;
        const int c = tid;
        float mx = -3.4e38f;
#pragma unroll
        for (int j = 0; j < KG; j++)
            mx = fmaxf(mx, g_TP[(size_t)srcs[it][j] * OC + c]);
        float Tn = g_TP[(size_t)n * OC + c];
        float Pn = g_TP[(size_t)n * OC + 256 + c];
        float v = mx - Tn + Pn + theta_b[c] + phi_b[c] + x[(size_t)n * CH + c];
        g_x1[(size_t)n * CH + c] = v;
        sx[it][c] = v;
    }
    __syncthreads();
    {   // stage 1: 8 nodes x 64 outputs = 512 outputs; 2 per thread sharing
        // the w1t load (nodes niA = tid>>6 and niB = niA+4)
        const int niA = tid >> 6, c = tid & 63;
        const int niB = niA + 4;
        float accA = b1[c];
        float accB = b1[c];
        const float* sxA = sx[niA];
        const float* sxB = sx[niB];
#pragma unroll 8
        for (int k = 0; k < 256; k++) {
            float w = g_w1t[k * 64 + c];
            accA = fmaf(w, sxA[k], accA);
            accB = fmaf(w, sxB[k], accB);
        }
        float rs = 1.f / sqrtf(v1[c] + 1e-5f);
        accA = fmaxf(accA, 0.f);
        st1[niA][c] = (accA - m1[c]) * rs * g1[c] + be1[c];
        accB = fmaxf(accB, 0.f);
        st1[niB][c] = (accB - m1[c]) * rs * g1[c] + be1[c];
    }
    __syncthreads();
    {   // stage 2: 8 nodes x 32 outputs = 256 threads, all active
        const int ni = tid >> 5, c = tid & 31;
        float acc = b2[c];
        const float* s1r = st1[ni];
#pragma unroll
        for (int k = 0; k < 64; k++) acc = fmaf(g_w2t[k * 32 + c], s1r[k], acc);
        acc = fmaxf(acc, 0.f);
        float rs = 1.f / sqrtf(v2[c] + 1e-5f);
        st2[ni][c] = (acc - m2[c]) * rs * g2[c] + be2[c];
    }
    __syncthreads();
    if (tid < 8) {     // stage 3
        float acc = b3[0];
#pragma unroll
        for (int k = 0; k < 32; k++) acc = fmaf(w3[k], st2[tid][k], acc);
        score_out[n0 + tid] = acc;
    }
}

// ---------------- bitonic helpers ----------------
__device__ __forceinline__ void cswap(unsigned long long& a, unsigned long long& b,
                                      unsigned int dir) {
    if ((unsigned int)(a > b) == dir) { unsigned long long t = a; a = b; b = t; }
}

// ---------------- per-batch top-512 (exact jax top_k semantics) ----------------
__global__ void topk_kernel(const float* __restrict__ score,
                            float* __restrict__ topk_vals) {
    __shared__ unsigned long long keys[NPER];
    const int b = blockIdx.x;
    const int tid = threadIdx.x;   // 1024
    for (int i = tid; i < NPER; i += 1024) {
        unsigned int u = __float_as_uint(score[b * NPER + i]);
        u = (u & 0x80000000u) ? ~u : (u | 0x80000000u);   // order-preserving
        keys[i] = ((unsigned long long)(~u) << 32) | (unsigned int)i;  // desc score, asc idx
    }
    for (int size = 2; size < NPER; size <<= 1) {
        unsigned int ddd = 1u ^ (unsigned int)(((unsigned)tid & (unsigned)(size >> 1)) != 0);
        for (int stride = size >> 1; stride > 0; stride >>= 1) {
            __syncthreads();
            int pos = 2 * tid - (tid & (stride - 1));
            cswap(keys[pos], keys[pos + stride], ddd);
        }
    }
    for (int stride = NPER >> 1; stride > 0; stride >>= 1) {
        __syncthreads();
        int pos = 2 * tid - (tid & (stride - 1));
        cswap(keys[pos], keys[pos + stride], 1u);
    }
    __syncthreads();
    if (tid < KTOP) {
        unsigned int idx = (unsigned int)(keys[tid] & 0xffffffffu);
        topk_vals[b * KTOP + tid] = score[b * NPER + idx];
        g_perm[b * KTOP + tid] = b * NPER + (int)idx;
    }
}

// ---------------- gather x_new / x_copy / xyz_sel ----------------
__global__ void gather_kernel(const float* __restrict__ x_origin,
                              const float* __restrict__ xyz,
                              float* __restrict__ out_xnew,
                              float* __restrict__ out_xcopy) {
    const int r = blockIdx.x;        // 0..4095
    const int c = threadIdx.x;       // 256
    const int p = g_perm[r];
    out_xnew[(size_t)r * CH + c]  = g_x1[(size_t)p * CH + c];
    out_xcopy[(size_t)r * CH + c] = x_origin[(size_t)p * CH + c];
    if (c < 3) g_xyz_sel[r * 3 + c] = xyz[p * 3 + c];
}

// ---------------- 32-NN among the 512 selected points (per batch) ----------------
// d2 uses UNFUSED IEEE ops to match XLA's non-contracted sequential reduce so the
// sort keys (and thus the argsort output) are bitwise identical.
__global__ void knn_kernel(float* __restrict__ out_knn) {
    __shared__ float sxp[KTOP], syp[KTOP], szp[KTOP];
    __shared__ unsigned long long keys[KTOP];
    const int b = blockIdx.x >> 9;
    const int i = blockIdx.x & 511;
    const int tid = threadIdx.x;   // 256
    for (int t = tid; t < KTOP; t += 256) {
        int base = (b * KTOP + t) * 3;
        sxp[t] = g_xyz_sel[base]; syp[t] = g_xyz_sel[base + 1]; szp[t] = g_xyz_sel[base + 2];
    }
    __syncthreads();
    float xi = sxp[i], yi = syp[i], zi = szp[i];
    for (int t = tid; t < KTOP; t += 256) {
        float dx = __fsub_rn(xi, sxp[t]);
        float dy = __fsub_rn(yi, syp[t]);
        float dz = __fsub_rn(zi, szp[t]);
        float d2 = __fadd_rn(__fadd_rn(__fmul_rn(dx, dx), __fmul_rn(dy, dy)),
                             __fmul_rn(dz, dz));   // >= 0, unfused IEEE
        keys[t] = ((unsigned long long)__float_as_uint(d2) << 32) | (unsigned int)t;
    }
    for (int size = 2; size < KTOP; size <<= 1) {
        unsigned int ddd = 1u ^ (unsigned int)(((unsigned)tid & (unsigned)(size >> 1)) != 0);
        for (int stride = size >> 1; stride > 0; stride >>= 1) {
            __syncthreads();
            int pos = 2 * tid - (tid & (stride - 1));
            cswap(keys[pos], keys[pos + stride], ddd);
        }
    }
    for (int stride = KTOP >> 1; stride > 0; stride >>= 1) {
        __syncthreads();
        int pos = 2 * tid - (tid & (stride - 1));
        cswap(keys[pos], keys[pos + stride], 1u);
    }
    __syncthreads();
    if (tid < KNNK)
        out_knn[(size_t)blockIdx.x * KNNK + tid] =
            (float)(unsigned int)(keys[tid] & 0xffffffffu);
}

// ---------------- launch ----------------
extern "C" void kernel_launch(void* const* d_in, const int* in_sizes, int n_in,
                              void* d_out, int out_size) {
    const float* x        = (const float*)d_in[0];
    const float* x_origin = (const float*)d_in[1];
    const float* xyz      = (const float*)d_in[2];
    const int*   edge_src = (const int*)d_in[3];
    // d_in[4] = edge_dst (structure known: node n owns edges [16n,16n+16))
    const float* theta_w  = (const float*)d_in[5];
    const float* theta_b  = (const float*)d_in[6];
    const float* phi_w    = (const float*)d_in[7];
    const float* phi_b    = (const float*)d_in[8];
    const float* w1  = (const float*)d_in[9];
    const float* b1  = (const float*)d_in[10];
    const float* g1  = (const float*)d_in[11];
    const float* be1 = (const float*)d_in[12];
    const float* m1  = (const float*)d_in[13];
    const float* v1  = (const float*)d_in[14];
    const float* w2  = (const float*)d_in[15];
    const float* b2  = (const float*)d_in[16];
    const float* g2  = (const float*)d_in[17];
    const float* be2 = (const float*)d_in[18];
    const float* m2  = (const float*)d_in[19];
    const float* v2  = (const float*)d_in[20];
    const float* w3  = (const float*)d_in[21];
    const float* b3  = (const float*)d_in[22];

    float* out = (float*)d_out;
    float* out_knn   = out;                                   // 8*512*32   = 131072
    float* out_xnew  = out + 131072;                          // 8*512*256  = 1048576
    float* out_xcopy = out + 131072 + 1048576;                // 8*512*256  = 1048576
    float* out_score = out + 131072 + 2 * 1048576;            // 8*2048     = 16384
    float* out_topkv = out_score + 16384;                     // 8*512      = 4096

    transpose_w<<<64, 256>>>(w1, w2);
    dim3 ggrid(8, 128);
    gemm_tp<<<ggrid, 256>>>(x, theta_w, phi_w);
    edgemax_mlp<<<N_TOT / 8, 256>>>(x, edge_src, theta_b, phi_b,
                                    b1, g1, be1, m1, v1,
                                    b2, g2, be2, m2, v2, w3, b3, out_score);
    topk_kernel<<<BATCH, 1024>>>(out_score, out_topkv);
    gather_kernel<<<BATCH * KTOP, 256>>>(x_origin, xyz, out_xnew, out_xcopy);
    knn_kernel<<<BATCH * KTOP, 256>>>(out_knn);
}

// round 17
// speedup vs baseline: 1.1725x; 1.0781x over previous
#include <cuda_runtime.h>
#include <cstdint>

#define N_TOT 16384
#define NPER  2048
#define BATCH 8
#define CH    256
#define KG    16
#define KTOP  512
#define KNNK  32
#define OC    512   // T (256) | P (256)

// ---------------- scratch (no allocs allowed) ----------------
__device__ float g_TP[N_TOT * OC];        // 32 MB
__device__ float g_x1[N_TOT * CH];        // 16 MB
__device__ int   g_perm[BATCH * KTOP];
__device__ float g_xyz_sel[BATCH * KTOP * 3];
__device__ float g_w1t[256 * 64];         // w1 transposed: [k][c]
__device__ float g_w2t[64 * 32];          // w2 transposed: [k][c]
__device__ unsigned long long g_runs[BATCH * NPER];  // sorted 512-chunks

// ---------------- transpose w1/w2 for coalesced MLP reads ----------------
__global__ void transpose_w(const float* __restrict__ w1,
                            const float* __restrict__ w2) {
    int t = blockIdx.x * 256 + threadIdx.x;
    if (t < 64 * 256) {            // w1[r][k], r<64, k<256
        int r = t >> 8, k = t & 255;
        g_w1t[k * 64 + r] = w1[t];
    }
    if (t < 32 * 64) {             // w2[r][k], r<32, k<64
        int r = t >> 6, k = t & 63;
        g_w2t[k * 32 + r] = w2[t];
    }
}

// ---------------- f32x2 helpers (Blackwell FFMA2) ----------------
__device__ __forceinline__ unsigned long long pk2(float lo, float hi) {
    unsigned long long r;
    asm("mov.b64 %0, {%1, %2};" : "=l"(r) : "f"(lo), "f"(hi));
    return r;
}
__device__ __forceinline__ unsigned long long ffma2(unsigned long long a,
                                                    unsigned long long b,
                                                    unsigned long long c) {
    unsigned long long d;
    asm("fma.rn.f32x2 %0, %1, %2, %3;" : "=l"(d) : "l"(a), "l"(b), "l"(c));
    return d;
}
__device__ __forceinline__ void upk2(unsigned long long v, float& lo, float& hi) {
    asm("mov.b64 {%0, %1}, %2;" : "=f"(lo), "=f"(hi) : "l"(v));
}

// ---------------- GEMM: TP[n][o] = sum_k X[n][k] * W[o][k] ----------------
// FROZEN at the R9/R13-passing 128x64 form (4 variants regressed).
__global__ void gemm_tp(const float* __restrict__ X,
                        const float* __restrict__ theta_w,
                        const float* __restrict__ phi_w) {
    __shared__ float As[16][132];   // [k][m], row stride 528B (16B-aligned)
    __shared__ float Bs[16][68];    // [k][n]
    const int m0 = blockIdx.y * 128;
    const int o0 = blockIdx.x * 64;
    const float* W = (o0 < 256) ? (theta_w + (size_t)o0 * 256)
                                : (phi_w + (size_t)(o0 - 256) * 256);
    const int t  = threadIdx.x;       // 0..255
    const int tx = t & 15;            // col group  (tx*4)
    const int ty = t >> 4;            // row group  (ty*8)

    unsigned long long acc[4][4];     // [row-pair][col]
#pragma unroll
    for (int i = 0; i < 4; i++)
#pragma unroll
        for (int j = 0; j < 4; j++) acc[i][j] = 0ull;

    for (int k0 = 0; k0 < 256; k0 += 16) {
#pragma unroll
        for (int q = 0; q < 2; q++) {
            int s = t + q * 256;
            int row = s >> 2;
            int kc = (s & 3) * 4;
            float4 v = *reinterpret_cast<const float4*>(
                X + (size_t)(m0 + row) * 256 + k0 + kc);
            As[kc + 0][row] = v.x; As[kc + 1][row] = v.y;
            As[kc + 2][row] = v.z; As[kc + 3][row] = v.w;
        }
        {
            int row = t >> 2;
            int kc = (t & 3) * 4;
            float4 v = *reinterpret_cast<const float4*>(
                W + (size_t)row * 256 + k0 + kc);
            Bs[kc + 0][row] = v.x; Bs[kc + 1][row] = v.y;
            Bs[kc + 2][row] = v.z; Bs[kc + 3][row] = v.w;
        }
        __syncthreads();
#pragma unroll
        for (int kk = 0; kk < 16; kk++) {
            ulonglong2 a01 = *reinterpret_cast<const ulonglong2*>(&As[kk][ty * 8]);
            ulonglong2 a23 = *reinterpret_cast<const ulonglong2*>(&As[kk][ty * 8 + 4]);
            float4 b = *reinterpret_cast<const float4*>(&Bs[kk][tx * 4]);
            unsigned long long ap[4] = {a01.x, a01.y, a23.x, a23.y};
            unsigned long long bd[4] = {pk2(b.x, b.x), pk2(b.y, b.y),
                                        pk2(b.z, b.z), pk2(b.w, b.w)};
#pragma unroll
            for (int i = 0; i < 4; i++)
#pragma unroll
                for (int j = 0; j < 4; j++)
                    acc[i][j] = ffma2(ap[i], bd[j], acc[i][j]);
        }
        __syncthreads();
    }
#pragma unroll
    for (int i = 0; i < 4; i++) {
        int r0 = m0 + ty * 8 + 2 * i;
        float lo[4], hi[4];
#pragma unroll
        for (int j = 0; j < 4; j++) upk2(acc[i][j], lo[j], hi[j]);
        *reinterpret_cast<float4*>(&g_TP[(size_t)r0 * OC + o0 + tx * 4]) =
            make_float4(lo[0], lo[1], lo[2], lo[3]);
        *reinterpret_cast<float4*>(&g_TP[(size_t)(r0 + 1) * OC + o0 + tx * 4]) =
            make_float4(hi[0], hi[1], hi[2], hi[3]);
    }
}

// ---------------- EdgeConv max + residual + score MLP (fused) ----------------
// 8 nodes per block (R16-passing). Per-(n,c) arithmetic unchanged.
__global__ void edgemax_mlp(const float* __restrict__ x,
                            const int* __restrict__ edge_src,
                            const float* __restrict__ theta_b,
                            const float* __restrict__ phi_b,
                            const float* __restrict__ b1,
                            const float* __restrict__ g1, const float* __restrict__ be1,
                            const float* __restrict__ m1, const float* __restrict__ v1,
                            const float* __restrict__ b2,
                            const float* __restrict__ g2, const float* __restrict__ be2,
                            const float* __restrict__ m2, const float* __restrict__ v2,
                            const float* __restrict__ w3, const float* __restrict__ b3,
                            float* __restrict__ score_out) {
    const int n0 = blockIdx.x * 8;
    const int tid = threadIdx.x;   // 0..255
    __shared__ int   srcs[8][KG];
    __shared__ float sx[8][CH];
    __shared__ float st1[8][64];
    __shared__ float st2[8][32];
    if (tid < 8 * KG) srcs[tid >> 4][tid & 15] = edge_src[n0 * KG + tid];
    __syncthreads();
#pragma unroll
    for (int it = 0; it < 8; it++) {
        const int n = n0 + it;
        const int c = tid;
        float mx = -3.4e38f;
#pragma unroll
        for (int j = 0; j < KG; j++)
            mx = fmaxf(mx, g_TP[(size_t)srcs[it][j] * OC + c]);
        float Tn = g_TP[(size_t)n * OC + c];
        float Pn = g_TP[(size_t)n * OC + 256 + c];
        float v = mx - Tn + Pn + theta_b[c] + phi_b[c] + x[(size_t)n * CH + c];
        g_x1[(size_t)n * CH + c] = v;
        sx[it][c] = v;
    }
    __syncthreads();
    {   // stage 1: 2 outputs per thread sharing the w1t load
        const int niA = tid >> 6, c = tid & 63;
        const int niB = niA + 4;
        float accA = b1[c];
        float accB = b1[c];
        const float* sxA = sx[niA];
        const float* sxB = sx[niB];
#pragma unroll 8
        for (int k = 0; k < 256; k++) {
            float w = g_w1t[k * 64 + c];
            accA = fmaf(w, sxA[k], accA);
            accB = fmaf(w, sxB[k], accB);
        }
        float rs = 1.f / sqrtf(v1[c] + 1e-5f);
        accA = fmaxf(accA, 0.f);
        st1[niA][c] = (accA - m1[c]) * rs * g1[c] + be1[c];
        accB = fmaxf(accB, 0.f);
        st1[niB][c] = (accB - m1[c]) * rs * g1[c] + be1[c];
    }
    __syncthreads();
    {   // stage 2: 8 nodes x 32 outputs = 256 threads, all active
        const int ni = tid >> 5, c = tid & 31;
        float acc = b2[c];
        const float* s1r = st1[ni];
#pragma unroll
        for (int k = 0; k < 64; k++) acc = fmaf(g_w2t[k * 32 + c], s1r[k], acc);
        acc = fmaxf(acc, 0.f);
        float rs = 1.f / sqrtf(v2[c] + 1e-5f);
        st2[ni][c] = (acc - m2[c]) * rs * g2[c] + be2[c];
    }
    __syncthreads();
    if (tid < 8) {     // stage 3
        float acc = b3[0];
#pragma unroll
        for (int k = 0; k < 32; k++) acc = fmaf(w3[k], st2[tid][k], acc);
        score_out[n0 + tid] = acc;
    }
}

// ---------------- bitonic helpers ----------------
__device__ __forceinline__ void cswap(unsigned long long& a, unsigned long long& b,
                                      unsigned int dir) {
    if ((unsigned int)(a > b) == dir) { unsigned long long t = a; a = b; b = t; }
}

// ---------------- top-512 phase A: sort 512-chunks ascending ----------------
// key = (~order_transform(score))<<32 | batch_local_idx  (asc key = desc score,
// asc idx — identical key construction to the old single-kernel version).
__global__ void topk_sort_chunks(const float* __restrict__ score) {
    __shared__ unsigned long long keys[512];
    const int b = blockIdx.x >> 2;
    const int c = blockIdx.x & 3;
    const int tid = threadIdx.x;   // 256
#pragma unroll
    for (int q = 0; q < 2; q++) {
        int i = tid + q * 256;
        int gi = c * 512 + i;      // batch-local index
        unsigned int u = __float_as_uint(score[b * NPER + gi]);
        u = (u & 0x80000000u) ? ~u : (u | 0x80000000u);
        keys[i] = ((unsigned long long)(~u) << 32) | (unsigned int)gi;
    }
    for (int size = 2; size < 512; size <<= 1) {
        unsigned int ddd = 1u ^ (unsigned int)(((unsigned)tid & (unsigned)(size >> 1)) != 0);
        for (int stride = size >> 1; stride > 0; stride >>= 1) {
            __syncthreads();
            int pos = 2 * tid - (tid & (stride - 1));
            cswap(keys[pos], keys[pos + stride], ddd);
        }
    }
    for (int stride = 256; stride > 0; stride >>= 1) {
        __syncthreads();
        int pos = 2 * tid - (tid & (stride - 1));
        cswap(keys[pos], keys[pos + stride], 1u);
    }
    __syncthreads();
    g_runs[(size_t)(b * 4 + c) * 512 + tid] = keys[tid];
    g_runs[(size_t)(b * 4 + c) * 512 + tid + 256] = keys[tid + 256];
}

// ---------------- top-512 phase B: merge-select smallest 512 of 4 runs ------
// For sorted-asc A,B: min(A[i], B[511-i]) = smallest-512 of union as a bitonic
// sequence; a 9-stage bitonic merge then sorts it ascending. Exact selection on
// identical keys -> output identical to the full-2048 sort's first 512.
__global__ void topk_merge(const float* __restrict__ score,
                           float* __restrict__ topk_vals) {
    __shared__ unsigned long long s[2048];
    const int b = blockIdx.x;
    const int tid = threadIdx.x;   // 512
#pragma unroll
    for (int q = 0; q < 4; q++)
        s[tid + q * 512] = g_runs[(size_t)b * 2048 + tid + q * 512];
    __syncthreads();
    {   // pair select: pairs (run0,run1)->s[0..511], (run2,run3)->s[1024..1535]
        const int p = tid >> 8, j = tid & 255;
        const int base = p * 1024;
#pragma unroll
        for (int q = 0; q < 2; q++) {
            int i = j + q * 256;
            unsigned long long a = s[base + i];
            unsigned long long c2 = s[base + 512 + (511 - i)];
            s[base + i] = (a < c2) ? a : c2;
        }
    }
    for (int stride = 256; stride > 0; stride >>= 1) {
        __syncthreads();
        const int p = tid >> 8, j = tid & 255;
        const int base = p * 1024;
        int pos = 2 * j - (j & (stride - 1));
        cswap(s[base + pos], s[base + pos + stride], 1u);
    }
    __syncthreads();
    {   // final select: smallest 512 of the two lower halves
        unsigned long long a = s[tid];
        unsigned long long c2 = s[1024 + 511 - tid];
        s[tid] = (a < c2) ? a : c2;
    }
    for (int stride = 256; stride > 0; stride >>= 1) {
        __syncthreads();
        if (tid < 256) {
            int pos = 2 * tid - (tid & (stride - 1));
            cswap(s[pos], s[pos + stride], 1u);
        }
    }
    __syncthreads();
    {
        unsigned int idx = (unsigned int)(s[tid] & 0xffffffffu);
        topk_vals[b * KTOP + tid] = score[b * NPER + idx];
        g_perm[b * KTOP + tid] = b * NPER + (int)idx;
    }
}

// ---------------- gather x_new / x_copy / xyz_sel ----------------
__global__ void gather_kernel(const float* __restrict__ x_origin,
                              const float* __restrict__ xyz,
                              float* __restrict__ out_xnew,
                              float* __restrict__ out_xcopy) {
    const int r = blockIdx.x;        // 0..4095
    const int c = threadIdx.x;       // 256
    const int p = g_perm[r];
    out_xnew[(size_t)r * CH + c]  = g_x1[(size_t)p * CH + c];
    out_xcopy[(size_t)r * CH + c] = x_origin[(size_t)p * CH + c];
    if (c < 3) g_xyz_sel[r * 3 + c] = xyz[p * 3 + c];
}

// ---------------- 32-NN among the 512 selected points (per batch) ----------------
// d2 uses UNFUSED IEEE ops to match XLA's non-contracted sequential reduce so the
// sort keys (and thus the argsort output) are bitwise identical.
__global__ void knn_kernel(float* __restrict__ out_knn) {
    __shared__ float sxp[KTOP], syp[KTOP], szp[KTOP];
    __shared__ unsigned long long keys[KTOP];
    const int b = blockIdx.x >> 9;
    const int i = blockIdx.x & 511;
    const int tid = threadIdx.x;   // 256
    for (int t = tid; t < KTOP; t += 256) {
        int base = (b * KTOP + t) * 3;
        sxp[t] = g_xyz_sel[base]; syp[t] = g_xyz_sel[base + 1]; szp[t] = g_xyz_sel[base + 2];
    }
    __syncthreads();
    float xi = sxp[i], yi = syp[i], zi = szp[i];
    for (int t = tid; t < KTOP; t += 256) {
        float dx = __fsub_rn(xi, sxp[t]);
        float dy = __fsub_rn(yi, syp[t]);
        float dz = __fsub_rn(zi, szp[t]);
        float d2 = __fadd_rn(__fadd_rn(__fmul_rn(dx, dx), __fmul_rn(dy, dy)),
                             __fmul_rn(dz, dz));   // >= 0, unfused IEEE
        keys[t] = ((unsigned long long)__float_as_uint(d2) << 32) | (unsigned int)t;
    }
    for (int size = 2; size < KTOP; size <<= 1) {
        unsigned int ddd = 1u ^ (unsigned int)(((unsigned)tid & (unsigned)(size >> 1)) != 0);
        for (int stride = size >> 1; stride > 0; stride >>= 1) {
            __syncthreads();
            int pos = 2 * tid - (tid & (stride - 1));
            cswap(keys[pos], keys[pos + stride], ddd);
        }
    }
    for (int stride = KTOP >> 1; stride > 0; stride >>= 1) {
        __syncthreads();
        int pos = 2 * tid - (tid & (stride - 1));
        cswap(keys[pos], keys[pos + stride], 1u);
    }
    __syncthreads();
    if (tid < KNNK)
        out_knn[(size_t)blockIdx.x * KNNK + tid] =
            (float)(unsigned int)(keys[tid] & 0xffffffffu);
}

// ---------------- launch ----------------
extern "C" void kernel_launch(void* const* d_in, const int* in_sizes, int n_in,
                              void* d_out, int out_size) {
    const float* x        = (const float*)d_in[0];
    const float* x_origin = (const float*)d_in[1];
    const float* xyz      = (const float*)d_in[2];
    const int*   edge_src = (const int*)d_in[3];
    // d_in[4] = edge_dst (structure known: node n owns edges [16n,16n+16))
    const float* theta_w  = (const float*)d_in[5];
    const float* theta_b  = (const float*)d_in[6];
    const float* phi_w    = (const float*)d_in[7];
    const float* phi_b    = (const float*)d_in[8];
    const float* w1  = (const float*)d_in[9];
    const float* b1  = (const float*)d_in[10];
    const float* g1  = (const float*)d_in[11];
    const float* be1 = (const float*)d_in[12];
    const float* m1  = (const float*)d_in[13];
    const float* v1  = (const float*)d_in[14];
    const float* w2  = (const float*)d_in[15];
    const float* b2  = (const float*)d_in[16];
    const float* g2  = (const float*)d_in[17];
    const float* be2 = (const float*)d_in[18];
    const float* m2  = (const float*)d_in[19];
    const float* v2  = (const float*)d_in[20];
    const float* w3  = (const float*)d_in[21];
    const float* b3  = (const float*)d_in[22];

    float* out = (float*)d_out;
    float* out_knn   = out;                                   // 8*512*32   = 131072
    float* out_xnew  = out + 131072;                          // 8*512*256  = 1048576
    float* out_xcopy = out + 131072 + 1048576;                // 8*512*256  = 1048576
    float* out_score = out + 131072 + 2 * 1048576;            // 8*2048     = 16384
    float* out_topkv = out_score + 16384;                     // 8*512      = 4096

    transpose_w<<<64, 256>>>(w1, w2);
    dim3 ggrid(8, 128);
    gemm_tp<<<ggrid, 256>>>(x, theta_w, phi_w);
    edgemax_mlp<<<N_TOT / 8, 256>>>(x, edge_src, theta_b, phi_b,
                                    b1, g1, be1, m1, v1,
                                    b2, g2, be2, m2, v2, w3, b3, out_score);
    topk_sort_chunks<<<BATCH * 4, 256>>>(out_score);
    topk_merge<<<BATCH, 512>>>(out_score, out_topkv);
    gather_kernel<<<BATCH * KTOP, 256>>>(x_origin, xyz, out_xnew, out_xcopy);
    knn_kernel<<<BATCH * KTOP, 256>>>(out_knn);
}